// round 15
// baseline (speedup 1.0000x reference)
#include <cuda_runtime.h>
#include <cstdint>
#include <cstddef>

#define T_ 1024
#define B_ 128
#define V_ 128
#define F_ 138
#define FP_ 160            // F padded to multiple of 32
#define H_ 1024
#define MLP_ 128
#define NCTA 128
#define NGRP 32
#define NTHR 256
#define AST 36             // smem row stride (floats)
#define STAGE_FLOATS (128 * AST + 256 * AST)  // A 128x36 + B 256x36 = 13824 floats
#define NSTAGE 3
#define RNN_SMEM (STAGE_FLOATS * NSTAGE * 4)  // 165888 B
#define MLP_SMEM ((128 * 132 + 128 * 36) * 4) // 86016 B

// ------------- device scratch (allocation-free rule: __device__ globals) -------------
__device__ float g_xc[(size_t)T_ * B_ * FP_];   // x tf32-rounded, padded to 160
__device__ float g_Wih1[4 * H_ * FP_];          // W_ih1 tf32, padded to 160
__device__ float g_Whh1[4 * H_ * H_];
__device__ float g_Wih2[4 * H_ * H_];
__device__ float g_Whh2[4 * H_ * H_];
__device__ float g_W1c[MLP_ * H_];
__device__ float g_h1[2][B_ * H_];
__device__ float g_h2[2][B_ * H_];
__device__ float g_H2[(size_t)T_ * B_ * H_];    // all h2_t for deferred MLP head
// partial exchange: [group][src(4)][own(4)][acc(2)][wm(2)][q(4)][mt(4)][lane(32)] float4
__device__ float4 g_part4[(size_t)NGRP * 4 * 4 * 2 * 2 * 4 * 4 * 32];
__device__ unsigned g_bar_cnt;
__device__ unsigned g_bar_gen;

// ------------- helpers -------------
__device__ __forceinline__ float tf32r(float f) {
    unsigned u;
    asm("cvt.rna.tf32.f32 %0, %1;" : "=r"(u) : "f"(f));
    return __uint_as_float(u);
}

__device__ __forceinline__ void mma8(float* c, unsigned a0, unsigned a1, unsigned a2,
                                     unsigned a3, unsigned b0, unsigned b1) {
    asm volatile(
        "mma.sync.aligned.m16n8k8.row.col.f32.tf32.tf32.f32 "
        "{%0,%1,%2,%3},{%4,%5,%6,%7},{%8,%9},{%0,%1,%2,%3};"
        : "+f"(c[0]), "+f"(c[1]), "+f"(c[2]), "+f"(c[3])
        : "r"(a0), "r"(a1), "r"(a2), "r"(a3), "r"(b0), "r"(b1));
}

__device__ __forceinline__ float sigm(float x) { return 1.f / (1.f + expf(-x)); }

__device__ __forceinline__ void cp16(uint32_t s, const float* g) {
    asm volatile("cp.async.cg.shared.global [%0], [%1], 16;" :: "r"(s), "l"(g));
}
__device__ __forceinline__ void cpcommit() { asm volatile("cp.async.commit_group;"); }
template <int N>
__device__ __forceinline__ void cpwait() {
    asm volatile("cp.async.wait_group %0;" :: "n"(N));
}

// software grid barrier — safe: 128 CTAs <= 148 SMs, single wave, all resident
__device__ __forceinline__ void grid_sync() {
    __threadfence();
    __syncthreads();
    if (threadIdx.x == 0) {
        unsigned gen = *(volatile unsigned*)&g_bar_gen;
        if (atomicAdd(&g_bar_cnt, 1u) == NCTA - 1) {
            g_bar_cnt = 0u;
            __threadfence();
            *(volatile unsigned*)&g_bar_gen = gen + 1u;
        } else {
            while (*(volatile unsigned*)&g_bar_gen == gen) __nanosleep(32);
        }
        __threadfence();
    }
    __syncthreads();
}

// schedule ids: s in [0,8) dual h1@{Whh1->acc1, Wih2->acc2}; [8,16) h2@Whh2->acc2;
//               [16,16+nx) x@Wih1->acc1. K ranges split 4-ways by rank.
__device__ __forceinline__ void do_fill(uint32_t sbase, int s, int rank, int group,
                                        const float* __restrict__ h1b,
                                        const float* __restrict__ h2b,
                                        const float* __restrict__ xb, int tid) {
    const float *A, *W0, *W1 = nullptr;
    int lda, ldw, k;
    if (s < 8)       { A = h1b; lda = H_;  W0 = g_Whh1; W1 = g_Wih2; ldw = H_;  k = rank * 256 + s * 32; }
    else if (s < 16) { A = h2b; lda = H_;  W0 = g_Whh2;              ldw = H_;  k = rank * 256 + (s - 8) * 32; }
    else             { A = xb;  lda = FP_; W0 = g_Wih1;              ldw = FP_; k = (rank ? 32 + rank * 32 : 0) + (s - 16) * 32; }
    const uint32_t Asb = sbase;
    const uint32_t Bsb = sbase + 128 * AST * 4;
#pragma unroll
    for (int i = tid; i < 1024; i += NTHR) {        // A: 128 rows x 8 float4
        int row = i >> 3, c4 = (i & 7) << 2;
        cp16(Asb + (uint32_t)(row * AST + c4) * 4, A + (size_t)row * lda + k + c4);
    }
#pragma unroll
    for (int i = tid; i < 1024; i += NTHR) {        // B lower: 128 rows x 8 float4
        int r = i >> 3, c4 = (i & 7) << 2;
        int n = ((r >> 3) & 3) * H_ + group * 32 + (r >> 5) * 8 + (r & 7);
        cp16(Bsb + (uint32_t)(r * AST + c4) * 4, W0 + (size_t)n * ldw + k + c4);
    }
    if (W1) {
#pragma unroll
        for (int i = tid; i < 1024; i += NTHR) {    // B upper: 128 rows x 8 float4
            int r = i >> 3, c4 = (i & 7) << 2;
            int n = ((r >> 3) & 3) * H_ + group * 32 + (r >> 5) * 8 + (r & 7);
            cp16(Bsb + (uint32_t)((128 + r) * AST + c4) * 4, W1 + (size_t)n * ldw + k + c4);
        }
    }
}

// warp tiling (2M x 4N): warp (wm in [0,2), wn in [0,4)) covers rows [wm*64,+64), cols [wn*32,+32)
// acc[q][mt*4 + c] : q = gate (col q*8), mt in [0,4) (row tile of 16), c = m16n8 C-frag index
template <bool DUAL>
__device__ __forceinline__ void compute_stage(float accL[4][16], float accU[4][16],
                                              const float* __restrict__ stage,
                                              int wm, int wn, int g, int tc) {
    const float* As = stage;
    const float* Bs = stage + 128 * AST;
#pragma unroll
    for (int ks = 0; ks < 32; ks += 8) {
        unsigned a[4][4];
#pragma unroll
        for (int mt = 0; mt < 4; mt++) {
            int rb = wm * 64 + mt * 16;
            a[mt][0] = __float_as_uint(As[(rb + g) * AST + ks + tc]);
            a[mt][1] = __float_as_uint(As[(rb + g + 8) * AST + ks + tc]);
            a[mt][2] = __float_as_uint(As[(rb + g) * AST + ks + tc + 4]);
            a[mt][3] = __float_as_uint(As[(rb + g + 8) * AST + ks + tc + 4]);
        }
#pragma unroll
        for (int q = 0; q < 4; q++) {
            int br = wn * 32 + q * 8 + g;
            unsigned b0 = __float_as_uint(Bs[br * AST + ks + tc]);
            unsigned b1 = __float_as_uint(Bs[br * AST + ks + tc + 4]);
#pragma unroll
            for (int mt = 0; mt < 4; mt++)
                mma8(&accL[q][mt * 4], a[mt][0], a[mt][1], a[mt][2], a[mt][3], b0, b1);
            if (DUAL) {
                unsigned u0 = __float_as_uint(Bs[(128 + br) * AST + ks + tc]);
                unsigned u1 = __float_as_uint(Bs[(128 + br) * AST + ks + tc + 4]);
#pragma unroll
                for (int mt = 0; mt < 4; mt++)
                    mma8(&accU[q][mt * 4], a[mt][0], a[mt][1], a[mt][2], a[mt][3], u0, u1);
            }
        }
    }
}

// pipelined pass over schedule ids [0, s1), s1 >= 16
__device__ __forceinline__ void fused_pass(int s1, int rank, int group,
                                           const float* h1b, const float* h2b, const float* xb,
                                           float* sm, int tid, int wm, int wn, int g, int tc,
                                           float acc1[4][16], float acc2[4][16]) {
    const uint32_t sb = (uint32_t)__cvta_generic_to_shared(sm);
    do_fill(sb, 0, rank, group, h1b, h2b, xb, tid);
    cpcommit();
    do_fill(sb + STAGE_FLOATS * 4, 1, rank, group, h1b, h2b, xb, tid);
    cpcommit();
    for (int s = 0; s < s1; s++) {
        if (s + 2 < s1) {
            do_fill(sb + (uint32_t)(((s + 2) % 3) * STAGE_FLOATS) * 4, s + 2, rank, group,
                    h1b, h2b, xb, tid);
            cpcommit();
            cpwait<2>();
        } else if (s + 1 < s1) {
            cpwait<1>();
        } else {
            cpwait<0>();
        }
        __syncthreads();
        const float* stg = sm + (s % 3) * STAGE_FLOATS;
        if (s < 8)       compute_stage<true>(acc1, acc2, stg, wm, wn, g, tc);
        else if (s < 16) compute_stage<false>(acc2, acc2, stg, wm, wn, g, tc);
        else             compute_stage<false>(acc1, acc1, stg, wm, wn, g, tc);
        __syncthreads();   // buffer s%3 refilled next iteration
    }
}

// ------------- partial exchange (float4 per lane, fragment layout) -------------
__device__ __forceinline__ float4* pslot(int group, int src, int own, int a, int wm,
                                         int q, int mt) {
    size_t idx = ((((((size_t)group * 4 + src) * 4 + own) * 2 + a) * 2 + wm) * 4 + q) * 4 + mt;
    return g_part4 + idx * 32;
}

__device__ __forceinline__ void write_acc(const float A_[4][16], int a, int group, int rank,
                                          int own, int wm, int lane) {
#pragma unroll
    for (int q = 0; q < 4; q++)
#pragma unroll
        for (int mt = 0; mt < 4; mt++)
            pslot(group, rank, own, a, wm, q, mt)[lane] =
                make_float4(A_[q][mt * 4], A_[q][mt * 4 + 1], A_[q][mt * 4 + 2], A_[q][mt * 4 + 3]);
}

__device__ __forceinline__ void reduce_acc(float A_[4][16], int a, int group, int rank,
                                           int wm, int lane) {
#pragma unroll
    for (int src = 0; src < 4; src++) {
        if (src == rank) continue;
#pragma unroll
        for (int q = 0; q < 4; q++)
#pragma unroll
            for (int mt = 0; mt < 4; mt++) {
                float4 v = __ldcg(&pslot(group, src, rank, a, wm, q, mt)[lane]);
                A_[q][mt * 4] += v.x;
                A_[q][mt * 4 + 1] += v.y;
                A_[q][mt * 4 + 2] += v.z;
                A_[q][mt * 4 + 3] += v.w;
            }
    }
}

// epilogue on reducing warps (wn == rank): activation + cell update + h store
__device__ __forceinline__ void lstm_epi(float A_[4][16], float c[16],
                                         const float* __restrict__ bih,
                                         const float* __restrict__ bhh,
                                         float* __restrict__ hdst, float* __restrict__ h2dst,
                                         int group, int rank, int wm, int g, int tc) {
    float bias[4][2];
#pragma unroll
    for (int q = 0; q < 4; q++)
#pragma unroll
        for (int j = 0; j < 2; j++) {
            int n = q * H_ + group * 32 + rank * 8 + 2 * tc + j;
            bias[q][j] = __ldg(bih + n) + __ldg(bhh + n);
        }
#pragma unroll
    for (int mt = 0; mt < 4; mt++)
#pragma unroll
        for (int rh = 0; rh < 2; rh++)
#pragma unroll
            for (int j = 0; j < 2; j++) {
                int idx = mt * 4 + rh * 2 + j;
                float iv = sigm(A_[0][idx] + bias[0][j]);
                float fv = sigm(A_[1][idx] + bias[1][j]);
                float gv = tanhf(A_[2][idx] + bias[2][j]);
                float ov = sigm(A_[3][idx] + bias[3][j]);
                c[idx] = fv * c[idx] + iv * gv;
                float h = tf32r(ov * tanhf(c[idx]));
                int row = wm * 64 + mt * 16 + rh * 8 + g;
                int hu = group * 32 + rank * 8 + 2 * tc + j;
                hdst[row * H_ + hu] = h;
                if (h2dst) h2dst[(size_t)row * H_ + hu] = h;
            }
}

// ------------- persistent recurrent kernel -------------
__global__ void __launch_bounds__(NTHR, 1)
rnn_kernel(const float* __restrict__ b_ih1, const float* __restrict__ b_hh1,
           const float* __restrict__ b_ih2, const float* __restrict__ b_hh2) {
    extern __shared__ float sm[];
    const int tid = threadIdx.x, lane = tid & 31, wid = tid >> 5;
    const int wn = wid & 3, wm = wid >> 2;          // wn = owner slot, wm = row half
    const int g = lane >> 2, tc = lane & 3;
    const int rank = blockIdx.x & 3, group = blockIdx.x >> 2;
    const bool own = (wn == rank);
    const int nx = (rank == 0) ? 2 : 1;

    float c1[16], c2[16];
#pragma unroll
    for (int i = 0; i < 16; i++) { c1[i] = 0.f; c2[i] = 0.f; }

    float acc1[4][16], acc2[4][16];
#pragma unroll
    for (int q = 0; q < 4; q++)
#pragma unroll
        for (int i = 0; i < 16; i++) { acc1[q][i] = 0.f; acc2[q][i] = 0.f; }

    // prologue: acc1(0) = x(0) @ Wih1^T (this rank's K chunks), non-pipelined
    {
        const uint32_t sb = (uint32_t)__cvta_generic_to_shared(sm);
        for (int si = 0; si < nx; si++) {
            do_fill(sb, 16 + si, rank, group, g_h1[0], g_h2[0], g_xc, tid);
            cpcommit();
            cpwait<0>();
            __syncthreads();
            compute_stage<false>(acc1, acc1, sm, wm, wn, g, tc);
            __syncthreads();
        }
    }
    if (!own) write_acc(acc1, 0, group, rank, wn, wm, lane);
    grid_sync();
    if (own) {
        reduce_acc(acc1, 0, group, rank, wm, lane);
        lstm_epi(acc1, c1, b_ih1, b_hh1, g_h1[0], nullptr, group, rank, wm, g, tc);
    }
    grid_sync();

    for (int t = 0; t < T_; t++) {
        const int w = t & 1;
#pragma unroll
        for (int q = 0; q < 4; q++)
#pragma unroll
            for (int i = 0; i < 16; i++) { acc1[q][i] = 0.f; acc2[q][i] = 0.f; }

        const int s1 = (t + 1 < T_) ? 16 + nx : 16;
        // acc2 = h1(t)@Wih2 + h2(t-1)@Whh2 ; acc1 = h1(t)@Whh1 + x(t+1)@Wih1
        fused_pass(s1, rank, group, g_h1[w], g_h2[w ^ 1],
                   g_xc + (size_t)(t + 1) * B_ * FP_, sm, tid, wm, wn, g, tc, acc1, acc2);

        if (!own) {
            write_acc(acc1, 0, group, rank, wn, wm, lane);
            write_acc(acc2, 1, group, rank, wn, wm, lane);
        }
        grid_sync();
        if (own) {
            reduce_acc(acc2, 1, group, rank, wm, lane);
            lstm_epi(acc2, c2, b_ih2, b_hh2, g_h2[w], g_H2 + (size_t)t * B_ * H_,
                     group, rank, wm, g, tc);
            if (t + 1 < T_) {
                reduce_acc(acc1, 0, group, rank, wm, lane);
                lstm_epi(acc1, c1, b_ih1, b_hh1, g_h1[w ^ 1], nullptr, group, rank, wm, g, tc);
            }
        }
        grid_sync();
    }
}

// ------------- batched MLP head: out = selu(h2 @ W1^T + b1) @ W2^T + b2 -------------
__global__ void __launch_bounds__(NTHR, 1)
mlp_kernel(const float* __restrict__ b1, const float* __restrict__ W2,
           const float* __restrict__ b2, float* __restrict__ out) {
    extern __shared__ float smh[];
    float* As = smh;
    float* Bs = smh + 128 * AST;
    float* mid = smh;                 // 128*132 (reuses As/Bs region after sync)
    float* Bs2 = smh + 128 * 132;
    const int tid = threadIdx.x, lane = tid & 31, mb = (tid >> 5) * 16;
    const int g = lane >> 2, tc = lane & 3;
    const size_t r0 = (size_t)blockIdx.x * 128;

    float acc[16][4];
#pragma unroll
    for (int q = 0; q < 16; q++) acc[q][0] = acc[q][1] = acc[q][2] = acc[q][3] = 0.f;

    for (int k0 = 0; k0 < H_; k0 += 32) {
        __syncthreads();
        for (int i = tid; i < 128 * 8; i += NTHR) {
            int m = i >> 3, kv = (i & 7) * 4;
            *(float4*)&As[m * AST + kv] = __ldg((const float4*)(g_H2 + (r0 + m) * H_ + k0 + kv));
        }
        for (int i = tid; i < 128 * 8; i += NTHR) {
            int n = i >> 3, kv = (i & 7) * 4;
            *(float4*)&Bs[n * AST + kv] = __ldg((const float4*)(g_W1c + (size_t)n * H_ + k0 + kv));
        }
        __syncthreads();
#pragma unroll
        for (int ks = 0; ks < 32; ks += 8) {
            unsigned a0 = __float_as_uint(As[(mb + g) * AST + ks + tc]);
            unsigned a1 = __float_as_uint(As[(mb + g + 8) * AST + ks + tc]);
            unsigned a2 = __float_as_uint(As[(mb + g) * AST + ks + tc + 4]);
            unsigned a3 = __float_as_uint(As[(mb + g + 8) * AST + ks + tc + 4]);
#pragma unroll
            for (int q = 0; q < 16; q++) {
                unsigned b0 = __float_as_uint(Bs[(q * 8 + g) * AST + ks + tc]);
                unsigned bb = __float_as_uint(Bs[(q * 8 + g) * AST + ks + tc + 4]);
                mma8(acc[q], a0, a1, a2, a3, b0, bb);
            }
        }
    }
    __syncthreads();

    const float SELU_L = 1.0507009873554805f, SELU_A = 1.6732632423543772f;
#pragma unroll
    for (int q = 0; q < 16; q++)
#pragma unroll
        for (int rr = 0; rr < 2; rr++)
#pragma unroll
            for (int j = 0; j < 2; j++) {
                int row = mb + g + 8 * rr, col = q * 8 + 2 * tc + j;
                float v = acc[q][rr * 2 + j] + __ldg(b1 + col);
                v = (v > 0.f) ? SELU_L * v : SELU_L * SELU_A * (expf(v) - 1.f);
                mid[row * 132 + col] = tf32r(v);
            }

    float acc2[16][4];
#pragma unroll
    for (int q = 0; q < 16; q++) acc2[q][0] = acc2[q][1] = acc2[q][2] = acc2[q][3] = 0.f;

    for (int k0 = 0; k0 < MLP_; k0 += 32) {
        __syncthreads();
        for (int i = tid; i < 128 * 32; i += NTHR) {
            int n = i >> 5, kk = i & 31;
            Bs2[n * AST + kk] = tf32r(__ldg(W2 + (size_t)n * MLP_ + k0 + kk));
        }
        __syncthreads();
#pragma unroll
        for (int ks = 0; ks < 32; ks += 8) {
            unsigned a0 = __float_as_uint(mid[(mb + g) * 132 + k0 + ks + tc]);
            unsigned a1 = __float_as_uint(mid[(mb + g + 8) * 132 + k0 + ks + tc]);
            unsigned a2 = __float_as_uint(mid[(mb + g) * 132 + k0 + ks + tc + 4]);
            unsigned a3 = __float_as_uint(mid[(mb + g + 8) * 132 + k0 + ks + tc + 4]);
#pragma unroll
            for (int q = 0; q < 16; q++) {
                unsigned b0 = __float_as_uint(Bs2[(q * 8 + g) * AST + ks + tc]);
                unsigned bb = __float_as_uint(Bs2[(q * 8 + g) * AST + ks + tc + 4]);
                mma8(acc2[q], a0, a1, a2, a3, b0, bb);
            }
        }
    }

#pragma unroll
    for (int q = 0; q < 16; q++)
#pragma unroll
        for (int rr = 0; rr < 2; rr++)
#pragma unroll
            for (int j = 0; j < 2; j++) {
                int row = mb + g + 8 * rr, col = q * 8 + 2 * tc + j;
                out[(r0 + row) * V_ + col] = acc2[q][rr * 2 + j] + __ldg(b2 + col);
            }
}

// ------------- phase 0 kernels -------------
__global__ void conv_kernel(const float* __restrict__ src, float* __restrict__ dst, int n) {
    int i = blockIdx.x * blockDim.x + threadIdx.x;
    int str = gridDim.x * blockDim.x;
    for (; i < n; i += str) dst[i] = tf32r(src[i]);
}

__global__ void conv3_kernel(const float* __restrict__ s0, float* __restrict__ d0, int n0,
                             const float* __restrict__ s1, float* __restrict__ d1, int n1,
                             const float* __restrict__ s2, float* __restrict__ d2, int n2) {
    int i = blockIdx.x * blockDim.x + threadIdx.x;
    int str = gridDim.x * blockDim.x;
    int n = n0 + n1 + n2;
    for (; i < n; i += str) {
        if (i < n0) d0[i] = tf32r(s0[i]);
        else if (i < n0 + n1) d1[i - n0] = tf32r(s1[i - n0]);
        else d2[i - n0 - n1] = tf32r(s2[i - n0 - n1]);
    }
}

__global__ void conv_pad_kernel(const float* __restrict__ src, float* __restrict__ dst,
                                int rows, int kin, int kpad) {
    int i = blockIdx.x * blockDim.x + threadIdx.x;
    int str = gridDim.x * blockDim.x;
    int n = rows * kpad;
    for (; i < n; i += str) {
        int r = i / kpad, c = i - r * kpad;
        dst[i] = (c < kin) ? tf32r(src[(size_t)r * kin + c]) : 0.f;
    }
}

__global__ void zero_kernel() {
    int i = blockIdx.x * blockDim.x + threadIdx.x;
    int str = gridDim.x * blockDim.x;
    const int n = 2 * B_ * H_;
    for (int j = i; j < n; j += str) ((float*)g_h1)[j] = 0.f;
    for (int j = i; j < n; j += str) ((float*)g_h2)[j] = 0.f;
    if (i == 0) { g_bar_cnt = 0u; g_bar_gen = 0u; }
}

extern "C" void kernel_launch(void* const* d_in, const int* in_sizes, int n_in,
                              void* d_out, int out_size) {
    const float* x     = (const float*)d_in[0];
    const float* W_ih1 = (const float*)d_in[1];
    const float* b_ih1 = (const float*)d_in[2];
    const float* W_hh1 = (const float*)d_in[3];
    const float* b_hh1 = (const float*)d_in[4];
    const float* W_ih2 = (const float*)d_in[5];
    const float* b_ih2 = (const float*)d_in[6];
    const float* W_hh2 = (const float*)d_in[7];
    const float* b_hh2 = (const float*)d_in[8];
    const float* W1    = (const float*)d_in[9];
    const float* b1    = (const float*)d_in[10];
    const float* W2    = (const float*)d_in[11];
    const float* b2    = (const float*)d_in[12];
    float* out = (float*)d_out;

    cudaFuncSetAttribute(rnn_kernel, cudaFuncAttributeMaxDynamicSharedMemorySize, RNN_SMEM);
    cudaFuncSetAttribute(mlp_kernel, cudaFuncAttributeMaxDynamicSharedMemorySize, MLP_SMEM);

    void *p_xc, *p_wi1, *p_wh1, *p_wi2, *p_wh2, *p_w1;
    cudaGetSymbolAddress(&p_xc, g_xc);
    cudaGetSymbolAddress(&p_wi1, g_Wih1);
    cudaGetSymbolAddress(&p_wh1, g_Whh1);
    cudaGetSymbolAddress(&p_wi2, g_Wih2);
    cudaGetSymbolAddress(&p_wh2, g_Whh2);
    cudaGetSymbolAddress(&p_w1, g_W1c);

    // launch order fixed so rnn_kernel is launch index 5
    conv_pad_kernel<<<4096, NTHR>>>(x, (float*)p_xc, T_ * B_, F_, FP_);          // 0
    conv_pad_kernel<<<4096, NTHR>>>(W_ih1, (float*)p_wi1, 4 * H_, F_, FP_);      // 1
    conv_kernel<<<4096, NTHR>>>(W_hh1, (float*)p_wh1, 4 * H_ * H_);              // 2
    conv3_kernel<<<4096, NTHR>>>(W_ih2, (float*)p_wi2, 4 * H_ * H_,              // 3
                                 W_hh2, (float*)p_wh2, 4 * H_ * H_,
                                 W1, (float*)p_w1, MLP_ * H_);
    zero_kernel<<<512, NTHR>>>();                                                // 4
    rnn_kernel<<<NCTA, NTHR, RNN_SMEM>>>(b_ih1, b_hh1, b_ih2, b_hh2);            // 5
    mlp_kernel<<<T_, NTHR, MLP_SMEM>>>(b1, W2, b2, out);                         // 6
}

// round 17
// speedup vs baseline: 1.0398x; 1.0398x over previous
#include <cuda_runtime.h>
#include <cstdint>
#include <cstddef>

#define T_ 1024
#define B_ 128
#define V_ 128
#define F_ 138
#define FP_ 160            // F padded to multiple of 32
#define H_ 1024
#define MLP_ 128
#define NCTA 128
#define NPAIR 64
#define NTHR 256
#define AST 36             // smem row stride (floats)
#define STAGE_FLOATS (128 * AST + 128 * AST)  // A 128x36 + B 128x36 = 9216 floats
#define NSTAGE 4
#define RNN_SMEM (STAGE_FLOATS * NSTAGE * 4)  // 147456 B
#define MLP_SMEM ((128 * 132 + 128 * 36) * 4) // 86016 B

// ------------- device scratch (allocation-free rule: __device__ globals) -------------
__device__ float g_xc[(size_t)T_ * B_ * FP_];   // x tf32-rounded, padded to 160
__device__ float g_Wih1[4 * H_ * FP_];          // W_ih1 tf32, padded to 160
__device__ float g_Whh1[4 * H_ * H_];
__device__ float g_Wih2[4 * H_ * H_];
__device__ float g_Whh2[4 * H_ * H_];
__device__ float g_W1c[MLP_ * H_];
__device__ float g_h1[2][B_ * H_];
__device__ float g_h2[2][B_ * H_];
__device__ float g_H2[(size_t)T_ * B_ * H_];    // all h2_t for deferred MLP head
// partial-sum exchange: [pair][srcrank][acc][wm][q][mt][half][lane][2]
__device__ float g_part[(size_t)NPAIR * 2 * 2 * 4 * 4 * 2 * 2 * 32 * 2];
__device__ unsigned g_bar_cnt;
__device__ unsigned g_bar_gen;

// ------------- helpers -------------
__device__ __forceinline__ float tf32r(float f) {
    unsigned u;
    asm("cvt.rna.tf32.f32 %0, %1;" : "=r"(u) : "f"(f));
    return __uint_as_float(u);
}

__device__ __forceinline__ void mma8(float* c, unsigned a0, unsigned a1, unsigned a2,
                                     unsigned a3, unsigned b0, unsigned b1) {
    asm volatile(
        "mma.sync.aligned.m16n8k8.row.col.f32.tf32.tf32.f32 "
        "{%0,%1,%2,%3},{%4,%5,%6,%7},{%8,%9},{%0,%1,%2,%3};"
        : "+f"(c[0]), "+f"(c[1]), "+f"(c[2]), "+f"(c[3])
        : "r"(a0), "r"(a1), "r"(a2), "r"(a3), "r"(b0), "r"(b1));
}

__device__ __forceinline__ float sigm(float x) { return 1.f / (1.f + expf(-x)); }

__device__ __forceinline__ void cp16(uint32_t s, const float* g) {
    asm volatile("cp.async.cg.shared.global [%0], [%1], 16;" :: "r"(s), "l"(g));
}
__device__ __forceinline__ void cpcommit() { asm volatile("cp.async.commit_group;"); }
template <int N>
__device__ __forceinline__ void cpwait() {
    asm volatile("cp.async.wait_group %0;" :: "n"(N));
}

// software grid barrier — safe: 128 CTAs <= 148 SMs, single wave, all resident
__device__ __forceinline__ void grid_sync() {
    __threadfence();
    __syncthreads();
    if (threadIdx.x == 0) {
        unsigned gen = *(volatile unsigned*)&g_bar_gen;
        if (atomicAdd(&g_bar_cnt, 1u) == NCTA - 1) {
            g_bar_cnt = 0u;
            __threadfence();
            *(volatile unsigned*)&g_bar_gen = gen + 1u;
        } else {
            while (*(volatile unsigned*)&g_bar_gen == gen) __nanosleep(32);
        }
        __threadfence();
    }
    __syncthreads();
}

// schedule ids: s in [0,16) dual h1@{Whh1->acc1, Wih2->acc2}; [16,32) h2@Whh2->acc2;
//               [32,32+nx) x@Wih1->acc1.   K ranges split by pair rank.
__device__ __forceinline__ void do_fill(uint32_t sbase, int s, int rank,
                                        const float* __restrict__ h1b,
                                        const float* __restrict__ h2b,
                                        const float* __restrict__ xb,
                                        int pairbase, int tid) {
    const float *A, *W0, *W1 = nullptr;
    int lda, ldw, k;
    if (s < 16)      { A = h1b; lda = H_;  W0 = g_Whh1; W1 = g_Wih2; ldw = H_;  k = rank * 512 + s * 32; }
    else if (s < 32) { A = h2b; lda = H_;  W0 = g_Whh2;              ldw = H_;  k = rank * 512 + (s - 16) * 32; }
    else             { A = xb;  lda = FP_; W0 = g_Wih1;              ldw = FP_; k = (rank ? 96 : 0) + (s - 32) * 32; }
    const uint32_t Asb = sbase;
    const uint32_t Bsb = sbase + 128 * AST * 4;
#pragma unroll
    for (int i = tid; i < 1024; i += NTHR) {        // A: 128 rows x 8 float4
        int row = i >> 3, c4 = (i & 7) << 2;
        cp16(Asb + (uint32_t)(row * AST + c4) * 4, A + (size_t)row * lda + k + c4);
    }
#pragma unroll
    for (int i = tid; i < 512; i += NTHR) {         // B lower: 64 rows x 8 float4
        int r = i >> 3, c4 = (i & 7) << 2;
        int n = ((r >> 3) & 3) * H_ + pairbase + (r >> 5) * 8 + (r & 7);
        cp16(Bsb + (uint32_t)(r * AST + c4) * 4, W0 + (size_t)n * ldw + k + c4);
    }
    if (W1) {
#pragma unroll
        for (int i = tid; i < 512; i += NTHR) {     // B upper: 64 rows x 8 float4
            int r = i >> 3, c4 = (i & 7) << 2;
            int n = ((r >> 3) & 3) * H_ + pairbase + (r >> 5) * 8 + (r & 7);
            cp16(Bsb + (uint32_t)((64 + r) * AST + c4) * 4, W1 + (size_t)n * ldw + k + c4);
        }
    }
}

// warp tiling (4M x 2N): warp covers rows [wm*32,+32), cols [wn*32,+32)
template <bool DUAL>
__device__ __forceinline__ void compute_stage(float accL[4][8], float accU[4][8],
                                              const float* __restrict__ stage,
                                              int wm, int wn, int g, int tc) {
    const float* As = stage;
    const float* Bs = stage + 128 * AST;
#pragma unroll
    for (int ks = 0; ks < 32; ks += 8) {
        unsigned a[2][4];
#pragma unroll
        for (int mt = 0; mt < 2; mt++) {
            int rb = wm * 32 + mt * 16;
            a[mt][0] = __float_as_uint(As[(rb + g) * AST + ks + tc]);
            a[mt][1] = __float_as_uint(As[(rb + g + 8) * AST + ks + tc]);
            a[mt][2] = __float_as_uint(As[(rb + g) * AST + ks + tc + 4]);
            a[mt][3] = __float_as_uint(As[(rb + g + 8) * AST + ks + tc + 4]);
        }
#pragma unroll
        for (int q = 0; q < 4; q++) {
            int br = wn * 32 + q * 8 + g;
            unsigned b0 = __float_as_uint(Bs[br * AST + ks + tc]);
            unsigned b1 = __float_as_uint(Bs[br * AST + ks + tc + 4]);
            mma8(&accL[q][0], a[0][0], a[0][1], a[0][2], a[0][3], b0, b1);
            mma8(&accL[q][4], a[1][0], a[1][1], a[1][2], a[1][3], b0, b1);
            if (DUAL) {
                unsigned u0 = __float_as_uint(Bs[(64 + br) * AST + ks + tc]);
                unsigned u1 = __float_as_uint(Bs[(64 + br) * AST + ks + tc + 4]);
                mma8(&accU[q][0], a[0][0], a[0][1], a[0][2], a[0][3], u0, u1);
                mma8(&accU[q][4], a[1][0], a[1][1], a[1][2], a[1][3], u0, u1);
            }
        }
    }
}

// pipelined pass over schedule ids [s0, s1): 4-stage ring, ONE __syncthreads per iter.
// order per iter: cpwait(own chunks) -> sync (all chunks visible; prior compute done)
//                 -> fill stage s+3 (buffer (s-1)%4, WAR-safe) -> compute(s)
__device__ __forceinline__ void fused_pass(int s0, int s1, int rank,
                                           const float* h1b, const float* h2b, const float* xb,
                                           int pairbase, float* sm, int tid,
                                           int wm, int wn, int g, int tc,
                                           float acc1[4][8], float acc2[4][8]) {
    const uint32_t sb = (uint32_t)__cvta_generic_to_shared(sm);
    const int n = s1 - s0;
    const int npro = (n < 3) ? n : 3;
    for (int i = 0; i < npro; i++) {
        do_fill(sb + (uint32_t)(i * STAGE_FLOATS) * 4, s0 + i, rank, h1b, h2b, xb, pairbase, tid);
        cpcommit();
    }
    for (int s = 0; s < n; s++) {
        int rem = n - s - 1;              // groups that may stay outstanding
        if (rem >= 2)      cpwait<2>();
        else if (rem == 1) cpwait<1>();
        else               cpwait<0>();
        __syncthreads();
        if (s + 3 < n) {
            do_fill(sb + (uint32_t)(((s + 3) & 3) * STAGE_FLOATS) * 4, s0 + s + 3, rank,
                    h1b, h2b, xb, pairbase, tid);
            cpcommit();
        }
        const float* stg = sm + (s & 3) * STAGE_FLOATS;
        int sid = s0 + s;
        if (sid < 16)      compute_stage<true>(acc1, acc2, stg, wm, wn, g, tc);
        else if (sid < 32) compute_stage<false>(acc2, acc2, stg, wm, wn, g, tc);
        else               compute_stage<false>(acc1, acc1, stg, wm, wn, g, tc);
    }
}

// ------------- partial exchange (perfectly coalesced float2 layout) -------------
__device__ __forceinline__ float2* part_slot(int pair, int src, int a, int wm, int q,
                                             int mt, int half) {
    size_t idx = ((((((size_t)pair * 2 + src) * 2 + a) * 4 + wm) * 4 + q) * 2 + mt) * 2 + half;
    return ((float2*)g_part) + idx * 32;
}

__device__ __forceinline__ void write_peer(const float A_[4][8], int a, int pair, int rank,
                                           int wm, int lane) {
#pragma unroll
    for (int q = 0; q < 4; q++)
#pragma unroll
        for (int mt = 0; mt < 2; mt++)
#pragma unroll
            for (int half = 0; half < 2; half++) {
                float2 v = make_float2(A_[q][mt * 4 + half * 2], A_[q][mt * 4 + half * 2 + 1]);
                *(part_slot(pair, rank, a, wm, q, mt, half) + lane) = v;
            }
}

__device__ __forceinline__ void reduce_peer(float A_[4][8], int a, int pair, int rank,
                                            int wm, int lane) {
#pragma unroll
    for (int q = 0; q < 4; q++)
#pragma unroll
        for (int mt = 0; mt < 2; mt++)
#pragma unroll
            for (int half = 0; half < 2; half++) {
                float2 v = __ldcg(part_slot(pair, rank ^ 1, a, wm, q, mt, half) + lane);
                A_[q][mt * 4 + half * 2] += v.x;
                A_[q][mt * 4 + half * 2 + 1] += v.y;
            }
}

// epilogue for one layer on own-group warps: activation + cell update + h store
__device__ __forceinline__ void lstm_epilogue(float A_[4][8], float c[8], const float bias[4][2],
                                              float* __restrict__ hdst, float* __restrict__ h2dst,
                                              int wm, int g, int hu) {
#pragma unroll
    for (int mt = 0; mt < 2; mt++)
#pragma unroll
        for (int half = 0; half < 2; half++)
#pragma unroll
            for (int j = 0; j < 2; j++) {
                int idx = mt * 4 + half * 2 + j;
                float iv = sigm(A_[0][idx] + bias[0][j]);
                float fv = sigm(A_[1][idx] + bias[1][j]);
                float gv = tanhf(A_[2][idx] + bias[2][j]);
                float ov = sigm(A_[3][idx] + bias[3][j]);
                c[idx] = fv * c[idx] + iv * gv;
                float h = tf32r(ov * tanhf(c[idx]));
                int row = wm * 32 + mt * 16 + half * 8 + g;
                hdst[row * H_ + hu + j] = h;
                if (h2dst) h2dst[(size_t)row * H_ + hu + j] = h;
            }
}

// ------------- persistent recurrent kernel -------------
__global__ void __launch_bounds__(NTHR, 1)
rnn_kernel(const float* __restrict__ b_ih1, const float* __restrict__ b_hh1,
           const float* __restrict__ b_ih2, const float* __restrict__ b_hh2) {
    extern __shared__ float sm[];
    const int tid = threadIdx.x, lane = tid & 31, wid = tid >> 5;
    const int wm = wid & 3, wn = wid >> 2;
    const int g = lane >> 2, tc = lane & 3;
    const int rank = blockIdx.x & 1, pair = blockIdx.x >> 1;
    const int pairbase = pair * 16;
    const int hu = pairbase + rank * 8 + 2 * tc;   // this thread's first own hidden unit
    const bool own = (wn == rank);
    const int nx = rank ? 2 : 3;

    float bias1[4][2], bias2[4][2];
#pragma unroll
    for (int q = 0; q < 4; q++)
#pragma unroll
        for (int j = 0; j < 2; j++) {
            int n = q * H_ + hu + j;
            bias1[q][j] = __ldg(b_ih1 + n) + __ldg(b_hh1 + n);
            bias2[q][j] = __ldg(b_ih2 + n) + __ldg(b_hh2 + n);
        }

    float c1[8], c2[8];
#pragma unroll
    for (int i = 0; i < 8; i++) { c1[i] = 0.f; c2[i] = 0.f; }

    float acc1[4][8], acc2[4][8];
#pragma unroll
    for (int q = 0; q < 4; q++)
#pragma unroll
        for (int i = 0; i < 8; i++) { acc1[q][i] = 0.f; acc2[q][i] = 0.f; }

    // prologue: acc1(0) = x(0) @ Wih1^T (this rank's K chunks)
    fused_pass(32, 32 + nx, rank, g_h1[0], g_h2[0], g_xc, pairbase, sm,
               tid, wm, wn, g, tc, acc1, acc2);
    if (!own) write_peer(acc1, 0, pair, rank, wm, lane);
    grid_sync();
    if (own) {
        reduce_peer(acc1, 0, pair, rank, wm, lane);
        lstm_epilogue(acc1, c1, bias1, g_h1[0], nullptr, wm, g, hu);
    }
    grid_sync();

    for (int t = 0; t < T_; t++) {
        const int w = t & 1;
#pragma unroll
        for (int q = 0; q < 4; q++)
#pragma unroll
            for (int i = 0; i < 8; i++) { acc1[q][i] = 0.f; acc2[q][i] = 0.f; }

        const int s1 = (t + 1 < T_) ? 32 + nx : 32;
        // acc2 = h1(t)@Wih2 + h2(t-1)@Whh2 ; acc1 = h1(t)@Whh1 + x(t+1)@Wih1
        fused_pass(0, s1, rank, g_h1[w], g_h2[w ^ 1],
                   g_xc + (size_t)(t + 1) * B_ * FP_, pairbase, sm,
                   tid, wm, wn, g, tc, acc1, acc2);

        if (!own) {
            write_peer(acc1, 0, pair, rank, wm, lane);
            write_peer(acc2, 1, pair, rank, wm, lane);
        }
        grid_sync();
        if (own) {
            reduce_peer(acc2, 1, pair, rank, wm, lane);
            lstm_epilogue(acc2, c2, bias2, g_h2[w], g_H2 + (size_t)t * B_ * H_,
                          wm, g, hu);
            if (t + 1 < T_) {
                reduce_peer(acc1, 0, pair, rank, wm, lane);
                lstm_epilogue(acc1, c1, bias1, g_h1[w ^ 1], nullptr, wm, g, hu);
            }
        }
        grid_sync();
    }
}

// ------------- batched MLP head: out = selu(h2 @ W1^T + b1) @ W2^T + b2 -------------
__global__ void __launch_bounds__(NTHR, 1)
mlp_kernel(const float* __restrict__ b1, const float* __restrict__ W2,
           const float* __restrict__ b2, float* __restrict__ out) {
    extern __shared__ float smh[];
    float* As = smh;
    float* Bs = smh + 128 * AST;
    float* mid = smh;                 // 128*132 (reuses As/Bs region after sync)
    float* Bs2 = smh + 128 * 132;
    const int tid = threadIdx.x, lane = tid & 31, mb = (tid >> 5) * 16;
    const int g = lane >> 2, tc = lane & 3;
    const size_t r0 = (size_t)blockIdx.x * 128;

    float acc[16][4];
#pragma unroll
    for (int q = 0; q < 16; q++) acc[q][0] = acc[q][1] = acc[q][2] = acc[q][3] = 0.f;

    for (int k0 = 0; k0 < H_; k0 += 32) {
        __syncthreads();
        for (int i = tid; i < 128 * 8; i += NTHR) {
            int m = i >> 3, kv = (i & 7) * 4;
            *(float4*)&As[m * AST + kv] = __ldg((const float4*)(g_H2 + (r0 + m) * H_ + k0 + kv));
        }
        for (int i = tid; i < 128 * 8; i += NTHR) {
            int n = i >> 3, kv = (i & 7) * 4;
            *(float4*)&Bs[n * AST + kv] = __ldg((const float4*)(g_W1c + (size_t)n * H_ + k0 + kv));
        }
        __syncthreads();
#pragma unroll
        for (int ks = 0; ks < 32; ks += 8) {
            unsigned a0 = __float_as_uint(As[(mb + g) * AST + ks + tc]);
            unsigned a1 = __float_as_uint(As[(mb + g + 8) * AST + ks + tc]);
            unsigned a2 = __float_as_uint(As[(mb + g) * AST + ks + tc + 4]);
            unsigned a3 = __float_as_uint(As[(mb + g + 8) * AST + ks + tc + 4]);
#pragma unroll
            for (int q = 0; q < 16; q++) {
                unsigned b0 = __float_as_uint(Bs[(q * 8 + g) * AST + ks + tc]);
                unsigned bb = __float_as_uint(Bs[(q * 8 + g) * AST + ks + tc + 4]);
                mma8(acc[q], a0, a1, a2, a3, b0, bb);
            }
        }
    }
    __syncthreads();

    const float SELU_L = 1.0507009873554805f, SELU_A = 1.6732632423543772f;
#pragma unroll
    for (int q = 0; q < 16; q++)
#pragma unroll
        for (int rr = 0; rr < 2; rr++)
#pragma unroll
            for (int j = 0; j < 2; j++) {
                int row = mb + g + 8 * rr, col = q * 8 + 2 * tc + j;
                float v = acc[q][rr * 2 + j] + __ldg(b1 + col);
                v = (v > 0.f) ? SELU_L * v : SELU_L * SELU_A * (expf(v) - 1.f);
                mid[row * 132 + col] = tf32r(v);
            }

    float acc2[16][4];
#pragma unroll
    for (int q = 0; q < 16; q++) acc2[q][0] = acc2[q][1] = acc2[q][2] = acc2[q][3] = 0.f;

    for (int k0 = 0; k0 < MLP_; k0 += 32) {
        __syncthreads();
        for (int i = tid; i < 128 * 32; i += NTHR) {
            int n = i >> 5, kk = i & 31;
            Bs2[n * AST + kk] = tf32r(__ldg(W2 + (size_t)n * MLP_ + k0 + kk));
        }
        __syncthreads();
#pragma unroll
        for (int ks = 0; ks < 32; ks += 8) {
            unsigned a0 = __float_as_uint(mid[(mb + g) * 132 + k0 + ks + tc]);
            unsigned a1 = __float_as_uint(mid[(mb + g + 8) * 132 + k0 + ks + tc]);
            unsigned a2 = __float_as_uint(mid[(mb + g) * 132 + k0 + ks + tc + 4]);
            unsigned a3 = __float_as_uint(mid[(mb + g + 8) * 132 + k0 + ks + tc + 4]);
#pragma unroll
            for (int q = 0; q < 16; q++) {
                unsigned b0 = __float_as_uint(Bs2[(q * 8 + g) * AST + ks + tc]);
                unsigned bb = __float_as_uint(Bs2[(q * 8 + g) * AST + ks + tc + 4]);
                mma8(acc2[q], a0, a1, a2, a3, b0, bb);
            }
        }
    }

#pragma unroll
    for (int q = 0; q < 16; q++)
#pragma unroll
        for (int rr = 0; rr < 2; rr++)
#pragma unroll
            for (int j = 0; j < 2; j++) {
                int row = mb + g + 8 * rr, col = q * 8 + 2 * tc + j;
                out[(r0 + row) * V_ + col] = acc2[q][rr * 2 + j] + __ldg(b2 + col);
            }
}

// ------------- phase 0 kernels -------------
__global__ void conv_kernel(const float* __restrict__ src, float* __restrict__ dst, int n) {
    int i = blockIdx.x * blockDim.x + threadIdx.x;
    int str = gridDim.x * blockDim.x;
    for (; i < n; i += str) dst[i] = tf32r(src[i]);
}

__global__ void conv3_kernel(const float* __restrict__ s0, float* __restrict__ d0, int n0,
                             const float* __restrict__ s1, float* __restrict__ d1, int n1,
                             const float* __restrict__ s2, float* __restrict__ d2, int n2) {
    int i = blockIdx.x * blockDim.x + threadIdx.x;
    int str = gridDim.x * blockDim.x;
    int n = n0 + n1 + n2;
    for (; i < n; i += str) {
        if (i < n0) d0[i] = tf32r(s0[i]);
        else if (i < n0 + n1) d1[i - n0] = tf32r(s1[i - n0]);
        else d2[i - n0 - n1] = tf32r(s2[i - n0 - n1]);
    }
}

__global__ void conv_pad_kernel(const float* __restrict__ src, float* __restrict__ dst,
                                int rows, int kin, int kpad) {
    int i = blockIdx.x * blockDim.x + threadIdx.x;
    int str = gridDim.x * blockDim.x;
    int n = rows * kpad;
    for (; i < n; i += str) {
        int r = i / kpad, c = i - r * kpad;
        dst[i] = (c < kin) ? tf32r(src[(size_t)r * kin + c]) : 0.f;
    }
}

__global__ void zero_kernel() {
    int i = blockIdx.x * blockDim.x + threadIdx.x;
    int str = gridDim.x * blockDim.x;
    const int n = 2 * B_ * H_;
    for (int j = i; j < n; j += str) ((float*)g_h1)[j] = 0.f;
    for (int j = i; j < n; j += str) ((float*)g_h2)[j] = 0.f;
    if (i == 0) { g_bar_cnt = 0u; g_bar_gen = 0u; }
}

extern "C" void kernel_launch(void* const* d_in, const int* in_sizes, int n_in,
                              void* d_out, int out_size) {
    const float* x     = (const float*)d_in[0];
    const float* W_ih1 = (const float*)d_in[1];
    const float* b_ih1 = (const float*)d_in[2];
    const float* W_hh1 = (const float*)d_in[3];
    const float* b_hh1 = (const float*)d_in[4];
    const float* W_ih2 = (const float*)d_in[5];
    const float* b_ih2 = (const float*)d_in[6];
    const float* W_hh2 = (const float*)d_in[7];
    const float* b_hh2 = (const float*)d_in[8];
    const float* W1    = (const float*)d_in[9];
    const float* b1    = (const float*)d_in[10];
    const float* W2    = (const float*)d_in[11];
    const float* b2    = (const float*)d_in[12];
    float* out = (float*)d_out;

    cudaFuncSetAttribute(rnn_kernel, cudaFuncAttributeMaxDynamicSharedMemorySize, RNN_SMEM);
    cudaFuncSetAttribute(mlp_kernel, cudaFuncAttributeMaxDynamicSharedMemorySize, MLP_SMEM);

    void *p_xc, *p_wi1, *p_wh1, *p_wi2, *p_wh2, *p_w1;
    cudaGetSymbolAddress(&p_xc, g_xc);
    cudaGetSymbolAddress(&p_wi1, g_Wih1);
    cudaGetSymbolAddress(&p_wh1, g_Whh1);
    cudaGetSymbolAddress(&p_wi2, g_Wih2);
    cudaGetSymbolAddress(&p_wh2, g_Whh2);
    cudaGetSymbolAddress(&p_w1, g_W1c);

    // launch order fixed so rnn_kernel is launch index 5
    conv_pad_kernel<<<4096, NTHR>>>(x, (float*)p_xc, T_ * B_, F_, FP_);          // 0
    conv_pad_kernel<<<4096, NTHR>>>(W_ih1, (float*)p_wi1, 4 * H_, F_, FP_);      // 1
    conv_kernel<<<4096, NTHR>>>(W_hh1, (float*)p_wh1, 4 * H_ * H_);              // 2
    conv3_kernel<<<4096, NTHR>>>(W_ih2, (float*)p_wi2, 4 * H_ * H_,              // 3
                                 W_hh2, (float*)p_wh2, 4 * H_ * H_,
                                 W1, (float*)p_w1, MLP_ * H_);
    zero_kernel<<<512, NTHR>>>();                                                // 4
    rnn_kernel<<<NCTA, NTHR, RNN_SMEM>>>(b_ih1, b_hh1, b_ih2, b_hh2);            // 5
    mlp_kernel<<<T_, NTHR, MLP_SMEM>>>(b1, W2, b2, out);                         // 6
}